// round 14
// baseline (speedup 1.0000x reference)
#include <cuda_runtime.h>
#include <cuda_bf16.h>
#include <cstdint>

#define NN 256
#define FF 16
#define HH 2048
#define PP 16
#define EE 32768

// Scratch (device globals; allocation is forbidden).
// Zero at module load; every launch restores them to zero after use, so no
// init kernel is needed (self-restoring invariant across graph replays).
__device__ int4  d_A4[NN * NN / 4];   // edge-count matrix (NO self-loops), 256 KB
__device__ int   d_deg[NN];           // edge in-degree (NO self-loop)
__device__ int   d_rowctr[NN / 16];   // per-chunk consumption counters
__device__ float d_outh[NN * HH];     // agg @ W + b   (2 MB)

// ---------------------------------------------------------------------------
// K1: one edge per thread; spread global atomics onto zeroed A/deg.
// Block 0 also initializes q = bq for K3's atomic epilogue.
// Edge dtype probed at runtime (harness delivers int64 cast to int32).
// ---------------------------------------------------------------------------
__global__ __launch_bounds__(256) void k_edges(const void* __restrict__ ei_raw,
                                               const float* __restrict__ bq,
                                               float* __restrict__ q) {
    int t = threadIdx.x;
    if (blockIdx.x == 0) {            // q = bq (1024 float4)
        const float4* b4 = reinterpret_cast<const float4*>(bq);
        float4* q4 = reinterpret_cast<float4*>(q);
#pragma unroll
        for (int i = 0; i < 4; i++) q4[t + i * 256] = b4[t + i * 256];
    }

    const int*       e32 = (const int*)ei_raw;
    const long long* e64 = (const long long*)ei_raw;

    int probe = 0;
#pragma unroll
    for (int k = 0; k < 16; k++) probe |= e32[2 * k + 1];
    const bool is64 = (probe == 0);

    int e = blockIdx.x * 256 + t;     // 128 blocks -> e in [0, EE)
    int src, dst;
    if (is64) { src = (int)e64[e]; dst = (int)e64[EE + e]; }
    else      { src = e32[e];      dst = e32[EE + e];      }

    if ((unsigned)src < (unsigned)NN && (unsigned)dst < (unsigned)NN) {
        int* A = reinterpret_cast<int*>(d_A4);
        atomicAdd(&A[dst * NN + src], 1);
        atomicAdd(&d_deg[dst], 1);
    }
}

// ---------------------------------------------------------------------------
// K2: agg for a 16-node chunk, then out[n,h] = b[h] + sum_f agg[n,f]*W[f,h].
// Block (ht, nc), grid (8, 16). W is read ONCE per h-tile (L2 hot).
//   dinv[s] = rsqrt(deg[s]+1);  A has no self-loops -> add diagonal term.
// The last ht-block per chunk zeroes that chunk's A rows; chunk 0's last
// block also zeroes deg (self-restore; all readers use staged smem copies).
// ---------------------------------------------------------------------------
__global__ __launch_bounds__(256) void k_outh(const float* __restrict__ x,
                                              const float* __restrict__ W,
                                              const float* __restrict__ bias) {
    __shared__ float sdinv[NN];       // 1 KB
    __shared__ float sy[NN * FF];     // 16 KB (dinv-scaled x)
    __shared__ int   sA[16 * NN];     // 16 KB
    __shared__ float sagg[256];       // 1 KB (16 nodes x 16 f)
    __shared__ int   sflag;
    int t  = threadIdx.x;
    int ht = blockIdx.x;
    int nc = blockIdx.y;

    // dinv for all nodes (self-loop folded: deg+1)
    sdinv[t] = rsqrtf((float)(d_deg[t] + 1));

    // stage this chunk's 16 A-rows (1024 int4)
    int4* sA4 = reinterpret_cast<int4*>(sA);
#pragma unroll
    for (int i = 0; i < 4; i++) {
        int j = t + i * 256;
        sA4[j] = d_A4[nc * 1024 + j];
    }
    __syncthreads();

    if (t == 0) sflag = (atomicAdd(&d_rowctr[nc], 1) == 7);   // 8th of 8
    __syncthreads();

    // self-restore: last block of this chunk zeroes its A rows (+deg, ctr)
    if (sflag) {
#pragma unroll
        for (int i = 0; i < 4; i++)
            d_A4[nc * 1024 + t + i * 256] = make_int4(0, 0, 0, 0);
        if (t == 0) d_rowctr[nc] = 0;
        if (nc == 0) d_deg[t] = 0;    // any chunk's readers use smem copies
    }

    // stage y = dinv * x  (float4 j covers row j>>2; FF=16 -> 4 float4/row)
    const float4* gx4 = reinterpret_cast<const float4*>(x);
    float4* sy4 = reinterpret_cast<float4*>(sy);
#pragma unroll
    for (int i = 0; i < 4; i++) {
        int j = t + i * 256;
        float dv = sdinv[j >> 2];
        float4 v = gx4[j];
        v.x *= dv; v.y *= dv; v.z *= dv; v.w *= dv;
        sy4[j] = v;
    }
    __syncthreads();

    // agg[dl,f] = dinv[d] * (sum_s A[dl,s]*sy[s,f] + sy[d,f])  (diag +1)
    {
        int dl = t >> 4, f = t & 15;
        int d  = nc * 16 + dl;
        float acc = sy[d * FF + f];   // implicit self-loop
#pragma unroll 8
        for (int s = 0; s < NN; s++)
            acc += (float)sA[dl * NN + s] * sy[s * FF + f];
        sagg[t] = sdinv[d] * acc;
    }
    __syncthreads();

    // out for 16 nodes x 256 h
    int h = ht * 256 + t;
    float wc[FF];
#pragma unroll
    for (int f = 0; f < FF; f++) wc[f] = W[f * HH + h];
    float bh = bias[h];
#pragma unroll
    for (int nl = 0; nl < 16; nl++) {
        float v = bh;
#pragma unroll
        for (int f = 0; f < FF; f++) v = fmaf(sagg[nl * FF + f], wc[f], v);
        d_outh[(nc * 16 + nl) * HH + h] = v;
    }
}

// ---------------------------------------------------------------------------
// K3: q[n,p] += sum_h out[n,h] * Wq[n,h,p], warp-contiguous Wq walk.
// Flattened float4 view per node: idx -> h = idx>>2, p-group = (idx&3)*4.
// Warp accesses 32 consecutive float4 = 512B = 4 lines (minimal wavefronts).
// Grid 512 = (node, H-half); 512 threads; 4 accumulators per thread.
// ---------------------------------------------------------------------------
__global__ __launch_bounds__(512) void k_final(const float* __restrict__ Wq,
                                               float* __restrict__ q) {
    __shared__ float s_oh[1024];      // this block's outh half-row (4 KB)
    __shared__ float sred[16 * PP];   // per-warp partials
    int n    = blockIdx.x >> 1;
    int half = blockIdx.x & 1;
    int t    = threadIdx.x;

    if (t < 256)
        reinterpret_cast<float4*>(s_oh)[t] =
            reinterpret_cast<const float4*>(d_outh + n * HH + half * 1024)[t];
    __syncthreads();

    const float4* wq4 = reinterpret_cast<const float4*>(Wq)
                      + (size_t)n * (HH * PP / 4) + half * 4096;

    float a0 = 0.f, a1 = 0.f, a2 = 0.f, a3 = 0.f;
#pragma unroll
    for (int r = 0; r < 8; r++) {
        int idx = r * 512 + t;        // warp covers 32 consecutive float4
        float4 v = wq4[idx];
        float oh = s_oh[idx >> 2];
        a0 = fmaf(oh, v.x, a0);
        a1 = fmaf(oh, v.y, a1);
        a2 = fmaf(oh, v.z, a2);
        a3 = fmaf(oh, v.w, a3);
    }

    // reduce over lanes congruent mod 4 (p-group fixed = (lane&3)*4)
#pragma unroll
    for (int off = 16; off >= 4; off >>= 1) {
        a0 += __shfl_down_sync(0xffffffffu, a0, off);
        a1 += __shfl_down_sync(0xffffffffu, a1, off);
        a2 += __shfl_down_sync(0xffffffffu, a2, off);
        a3 += __shfl_down_sync(0xffffffffu, a3, off);
    }
    int lane = t & 31, wid = t >> 5;
    if (lane < 4) {
        sred[wid * PP + lane * 4 + 0] = a0;
        sred[wid * PP + lane * 4 + 1] = a1;
        sred[wid * PP + lane * 4 + 2] = a2;
        sred[wid * PP + lane * 4 + 3] = a3;
    }
    __syncthreads();
    if (t < PP) {
        float s = 0.0f;
#pragma unroll
        for (int w = 0; w < 16; w++) s += sred[w * PP + t];
        atomicAdd(&q[n * PP + t], s);
    }
}

// ---------------------------------------------------------------------------
extern "C" void kernel_launch(void* const* d_in, const int* in_sizes, int n_in,
                              void* d_out, int out_size) {
    const float* x    = (const float*)d_in[0];      // [256,16]
    const void*  ei   = d_in[1];                    // [2,32768] (int64 cast to int32)
    const float* W    = (const float*)d_in[2];      // [16,2048]
    const float* bias = (const float*)d_in[3];      // [2048]
    const float* Wq   = (const float*)d_in[4];      // [256,2048,16]
    const float* bq   = (const float*)d_in[5];      // [256,16]
    float*       q    = (float*)d_out;              // [256,16]

    k_edges<<<EE / 256, 256>>>(ei, bq, q);
    k_outh<<<dim3(8, 16), 256>>>(x, W, bias);
    k_final<<<2 * NN, 512>>>(Wq, q);
}

// round 17
// speedup vs baseline: 1.3439x; 1.3439x over previous
#include <cuda_runtime.h>
#include <cuda_bf16.h>
#include <cstdint>

#define NN 256
#define FF 16
#define HH 2048
#define PP 16
#define EE 32768
#define DR 8                          // deg replicas (contention 128 -> 16)

// Scratch (device globals; allocation is forbidden).
// Zero at module load; every launch restores them to zero after use, so no
// init kernel is needed (self-restoring invariant across graph replays).
__device__ int4  d_A4[NN * NN / 4];   // edge-count matrix (NO self-loops), 256 KB
__device__ int   d_degR[NN * DR];     // replicated in-degree (NO self-loop), 8 KB
__device__ int   d_rowctr[NN / 16];   // per-chunk consumption counters
__device__ int   d_allctr;            // global consumption counter (degR)
__device__ float d_outh[NN * HH];     // agg @ W + b   (2 MB)

// ---------------------------------------------------------------------------
// K1: one edge per thread; spread global atomics onto zeroed A/degR.
// Edge dtype probed at runtime (harness delivers int64 cast to int32).
// ---------------------------------------------------------------------------
__global__ __launch_bounds__(256) void k_edges(const void* __restrict__ ei_raw) {
    int t = threadIdx.x;

    const int*       e32 = (const int*)ei_raw;
    const long long* e64 = (const long long*)ei_raw;

    int probe = 0;
#pragma unroll
    for (int k = 0; k < 16; k++) probe |= e32[2 * k + 1];
    const bool is64 = (probe == 0);

    int e = blockIdx.x * 256 + t;     // 128 blocks -> e in [0, EE)
    int src, dst;
    if (is64) { src = (int)e64[e]; dst = (int)e64[EE + e]; }
    else      { src = e32[e];      dst = e32[EE + e];      }

    if ((unsigned)src < (unsigned)NN && (unsigned)dst < (unsigned)NN) {
        int* A = reinterpret_cast<int*>(d_A4);
        atomicAdd(&A[dst * NN + src], 1);
        atomicAdd(&d_degR[dst * DR + (t & (DR - 1))], 1);
    }
}

// ---------------------------------------------------------------------------
// K2: agg for a 16-node chunk, then out[n,h] = b[h] + sum_f agg[n,f]*W[f,h].
// Block (ht, nc), grid (8, 16). W is read ONCE per h-tile (L2 hot).
//   deg[s] = sum_r degR[s][r];  dinv[s] = rsqrt(deg[s]+1)  (+1 self-loop)
// Self-restore protocol (race-free):
//   - A rows of chunk nc: zeroed by the 8th block of chunk nc (only that
//     chunk's blocks read those rows).
//   - degR: read by ALL 128 blocks -> zeroed by the 128th block to finish
//     its reads (global counter d_allctr), which also resets the counter.
//   Counters are bumped only AFTER this block's reads are in smem (post-sync).
// ---------------------------------------------------------------------------
__global__ __launch_bounds__(256) void k_outh(const float* __restrict__ x,
                                              const float* __restrict__ W,
                                              const float* __restrict__ bias,
                                              const float* __restrict__ bq,
                                              float* __restrict__ q) {
    __shared__ float sdinv[NN];       // 1 KB
    __shared__ float sy[NN * FF];     // 16 KB (dinv-scaled x)
    __shared__ int   sA[16 * NN];     // 16 KB
    __shared__ float sagg[256];       // 1 KB (16 nodes x 16 f)
    __shared__ int   sflagA, sflagD;
    int t  = threadIdx.x;
    int ht = blockIdx.x;
    int nc = blockIdx.y;

    // q init (nc covers exactly 16 nodes x 16 p = 256 values)
    if (ht == 0) q[nc * 256 + t] = bq[nc * 256 + t];

    // dinv: sum the DR replicas (2 int4 loads), fold self-loop (+1)
    {
        const int4* g4 = reinterpret_cast<const int4*>(d_degR + t * DR);
        int4 r0 = g4[0], r1 = g4[1];
        int deg = r0.x + r0.y + r0.z + r0.w + r1.x + r1.y + r1.z + r1.w;
        sdinv[t] = rsqrtf((float)(deg + 1));
    }

    // stage this chunk's 16 A-rows (1024 int4)
    int4* sA4 = reinterpret_cast<int4*>(sA);
#pragma unroll
    for (int i = 0; i < 4; i++) {
        int j = t + i * 256;
        sA4[j] = d_A4[nc * 1024 + j];
    }
    __syncthreads();                  // all global reads of A/degR done

    if (t == 0) sflagA = (atomicAdd(&d_rowctr[nc], 1) == 7);    // 8th of 8
    if (t == 1) sflagD = (atomicAdd(&d_allctr, 1) == 127);      // 128th of 128
    __syncthreads();

    // self-restore to zero (all readers provably done)
    if (sflagA) {
#pragma unroll
        for (int i = 0; i < 4; i++)
            d_A4[nc * 1024 + t + i * 256] = make_int4(0, 0, 0, 0);
        if (t == 0) d_rowctr[nc] = 0;
    }
    if (sflagD) {
        int4* g4 = reinterpret_cast<int4*>(d_degR);  // 2048 ints = 512 int4
        g4[t] = make_int4(0, 0, 0, 0);
        g4[t + 256] = make_int4(0, 0, 0, 0);
        if (t == 0) d_allctr = 0;
    }

    // stage y = dinv * x  (float4 j covers row j>>2; FF=16 -> 4 float4/row)
    const float4* gx4 = reinterpret_cast<const float4*>(x);
    float4* sy4 = reinterpret_cast<float4*>(sy);
#pragma unroll
    for (int i = 0; i < 4; i++) {
        int j = t + i * 256;
        float dv = sdinv[j >> 2];
        float4 v = gx4[j];
        v.x *= dv; v.y *= dv; v.z *= dv; v.w *= dv;
        sy4[j] = v;
    }
    __syncthreads();

    // agg[dl,f] = dinv[d] * (sum_s A[dl,s]*sy[s,f] + sy[d,f])  (diag +1)
    {
        int dl = t >> 4, f = t & 15;
        int d  = nc * 16 + dl;
        float acc = sy[d * FF + f];   // implicit self-loop
#pragma unroll 8
        for (int s = 0; s < NN; s++)
            acc += (float)sA[dl * NN + s] * sy[s * FF + f];
        sagg[t] = sdinv[d] * acc;
    }
    __syncthreads();

    // out for 16 nodes x 256 h
    int h = ht * 256 + t;
    float wc[FF];
#pragma unroll
    for (int f = 0; f < FF; f++) wc[f] = W[f * HH + h];
    float bh = bias[h];
#pragma unroll
    for (int nl = 0; nl < 16; nl++) {
        float v = bh;
#pragma unroll
        for (int f = 0; f < FF; f++) v = fmaf(sagg[nl * FF + f], wc[f], v);
        d_outh[(nc * 16 + nl) * HH + h] = v;
    }
}

// ---------------------------------------------------------------------------
// K3: q[n,p] += sum_h out[n,h] * Wq[n,h,p], warp-contiguous Wq walk.
// Flattened float4 view per node: idx -> h = idx>>2, p-group = (idx&3)*4.
// Warp accesses 32 consecutive float4 = 512B = 4 lines (minimal wavefronts).
// Grid 512 = (node, H-half); 512 threads; 4 accumulators per thread.
// ---------------------------------------------------------------------------
__global__ __launch_bounds__(512) void k_final(const float* __restrict__ Wq,
                                               float* __restrict__ q) {
    __shared__ float s_oh[1024];      // this block's outh half-row (4 KB)
    __shared__ float sred[16 * PP];   // per-warp partials
    int n    = blockIdx.x >> 1;
    int half = blockIdx.x & 1;
    int t    = threadIdx.x;

    if (t < 256)
        reinterpret_cast<float4*>(s_oh)[t] =
            reinterpret_cast<const float4*>(d_outh + n * HH + half * 1024)[t];
    __syncthreads();

    const float4* wq4 = reinterpret_cast<const float4*>(Wq)
                      + (size_t)n * (HH * PP / 4) + half * 4096;

    float a0 = 0.f, a1 = 0.f, a2 = 0.f, a3 = 0.f;
#pragma unroll
    for (int r = 0; r < 8; r++) {
        int idx = r * 512 + t;        // warp covers 32 consecutive float4
        float4 v = wq4[idx];
        float oh = s_oh[idx >> 2];
        a0 = fmaf(oh, v.x, a0);
        a1 = fmaf(oh, v.y, a1);
        a2 = fmaf(oh, v.z, a2);
        a3 = fmaf(oh, v.w, a3);
    }

    // reduce over lanes congruent mod 4 (p-group fixed = (lane&3)*4)
#pragma unroll
    for (int off = 16; off >= 4; off >>= 1) {
        a0 += __shfl_down_sync(0xffffffffu, a0, off);
        a1 += __shfl_down_sync(0xffffffffu, a1, off);
        a2 += __shfl_down_sync(0xffffffffu, a2, off);
        a3 += __shfl_down_sync(0xffffffffu, a3, off);
    }
    int lane = t & 31, wid = t >> 5;
    if (lane < 4) {
        sred[wid * PP + lane * 4 + 0] = a0;
        sred[wid * PP + lane * 4 + 1] = a1;
        sred[wid * PP + lane * 4 + 2] = a2;
        sred[wid * PP + lane * 4 + 3] = a3;
    }
    __syncthreads();
    if (t < PP) {
        float s = 0.0f;
#pragma unroll
        for (int w = 0; w < 16; w++) s += sred[w * PP + t];
        atomicAdd(&q[n * PP + t], s);
    }
}

// ---------------------------------------------------------------------------
extern "C" void kernel_launch(void* const* d_in, const int* in_sizes, int n_in,
                              void* d_out, int out_size) {
    const float* x    = (const float*)d_in[0];      // [256,16]
    const void*  ei   = d_in[1];                    // [2,32768] (int64 cast to int32)
    const float* W    = (const float*)d_in[2];      // [16,2048]
    const float* bias = (const float*)d_in[3];      // [2048]
    const float* Wq   = (const float*)d_in[4];      // [256,2048,16]
    const float* bq   = (const float*)d_in[5];      // [256,16]
    float*       q    = (float*)d_out;              // [256,16]

    k_edges<<<EE / 256, 256>>>(ei);
    k_outh<<<dim3(8, 16), 256>>>(x, W, bias, bq, q);
    k_final<<<2 * NN, 512>>>(Wq, q);
}